// round 8
// baseline (speedup 1.0000x reference)
#include <cuda_runtime.h>
#include <math.h>

typedef unsigned long long u64;

#define BATCH 64
#define H 224
#define W 224
#define NPAIR 192
#define ACC_STRIDE 132
#define RW 232              // smem row width (4 guard cols each side, 4-aligned)
#define NRMAX 36
#define BANDS 7
#define BPK (BATCH * BANDS)             // 448 blocks per k
#define TOTAL_BLOCKS (5 * BPK)          // 2240
#define DYN_SMEM (3 * NRMAX * RW * 4)   // 100224 bytes

// Device scratch (no allocation allowed). Zero-initialized at module load;
// finalize_kernel re-zeroes g_acc after reading => every launch starts clean.
__device__ float g_feat[BATCH * 75];
__device__ int   g_acc[5 * NPAIR * ACC_STRIDE];

// Column masks for K=11 (stride 11, 128-bit mask in 2x u64)
constexpr u64 colmask_lo(int c) {
    u64 m = 0;
    for (int r = 0; r < 11; r++) { int p = r * 11 + c; if (p < 64) m |= 1ull << p; }
    return m;
}
constexpr u64 colmask_hi(int c) {
    u64 m = 0;
    for (int r = 0; r < 11; r++) { int p = r * 11 + c; if (p >= 64) m |= 1ull << (p - 64); }
    return m;
}
constexpr u64 NOTC0_LO  = ~colmask_lo(0);
constexpr u64 NOTC0_HI  = ~colmask_hi(0);
constexpr u64 NOTC10_LO = ~colmask_lo(10);
constexpr u64 NOTC10_HI = ~colmask_hi(10);

template <int K>
__device__ __forceinline__ void expand128(u64 clo, u64 chi, u64& glo, u64& ghi) {
    u64 l1lo = clo << 1;
    u64 l1hi = (chi << 1) | (clo >> 63);
    u64 r1lo = (clo >> 1) | (chi << 63);
    u64 r1hi = chi >> 1;
    if (K == 11) {
        l1lo &= NOTC0_LO;  l1hi &= NOTC0_HI;
        r1lo &= NOTC10_LO; r1hi &= NOTC10_HI;
    }
    u64 uplo = clo << 11;
    u64 uphi = (chi << 11) | (clo >> 53);
    u64 dnlo = (clo >> 11) | (chi << 53);
    u64 dnhi = chi >> 11;
    glo = l1lo | r1lo | uplo | dnlo;
    ghi = l1hi | r1hi | uphi | dnhi;
}

// ---------------------------------------------------------------------------
// Band body: block = (K, image b, row band). Loads band coalesced from NHWC,
// deinterleaves into 3 smem planes (zero guards), computes all patches in band.
// ---------------------------------------------------------------------------
template <int K, int BR, int SEG>
__device__ __forceinline__ void patch_band(const float4* __restrict__ in4,
                                           int rel, float* sm,
                                           int* shh /*3*128*/, int* shs /*9*/) {
    constexpr int ROWS = (H + K - 1) / K;
    constexpr int COLS = (W + K - 1) / K;
    constexpr int PADT = (ROWS * K - H) / 2;
    constexpr int PADL = (COLS * K - W) / 2;
    constexpr int KK   = K * K;
    constexpr int STRIDE = (K <= 7) ? 8 : 11;
    constexpr bool WIDE  = (K > 7);

    const int b    = rel / BANDS;
    const int band = rel % BANDS;
    const int tid  = threadIdx.x;

    const int i0    = band * BR;
    const int nbr   = (BR < ROWS - i0) ? BR : (ROWS - i0);
    const int NR    = nbr * K;
    const int rbase = i0 * K - PADT;
    const int plane = NR * RW;

    for (int i = tid; i < 3 * 128; i += 512) shh[i] = 0;
    if (tid < 9) shs[tid] = 0;

    // zero the used smem region
    {
        float4 z = make_float4(0.f, 0.f, 0.f, 0.f);
        float4* sm4 = (float4*)sm;
        const int nz = 3 * NR * (RW / 4);
        for (int i = tid; i < nz; i += 512) sm4[i] = z;
    }
    __syncthreads();

    // coalesced load + channel deinterleave
    {
        const int r_lo = (rbase < 0) ? 0 : rbase;
        const int r_hi = (rbase + NR > H) ? H : (rbase + NR);
        const int nload = (r_hi - r_lo) * 56;    // 56 float4-triplets per row
        const float4* src = in4 + b * (H * W * 3 / 4);
        for (int t = tid; t < nload; t += 512) {
            int s = t / 56, g = t - s * 56;
            int r = r_lo + s;
            int gb = r * 168 + 3 * g;
            float4 f0 = src[gb], f1 = src[gb + 1], f2 = src[gb + 2];
            int sb = (r - rbase) * RW + 4 + 4 * g;
            *(float4*)(sm + sb)             = make_float4(f0.x, f0.w, f1.z, f2.y);
            *(float4*)(sm + plane + sb)     = make_float4(f0.y, f1.x, f1.w, f2.z);
            *(float4*)(sm + 2 * plane + sb) = make_float4(f0.z, f1.y, f2.x, f2.w);
        }
    }
    __syncthreads();

    const int nbc = nbr * COLS;
    const int NP  = 3 * nbc;
    int cur_ch = 0, tnc = 0, tpc = 0, tma = 0;

    for (int pidx = tid; pidx < NP; pidx += 512) {
        int ch = pidx / nbc;
        int q  = pidx - ch * nbc;
        int il = q / COLS;
        int j  = q - il * COLS;

        if (ch != cur_ch) {
            if (tnc | tpc | tma) {
                atomicAdd(&shs[cur_ch * 3 + 0], tnc);
                atomicAdd(&shs[cur_ch * 3 + 1], tpc);
                atomicAdd(&shs[cur_ch * 3 + 2], tma);
            }
            tnc = tpc = tma = 0;
            cur_ch = ch;
        }

        const float* pl = sm + ch * plane + il * K * RW + (j * K - PADL + 4);
        const float center = pl[(K / 2) * RW + K / 2];
        const float lo = center - (float)K, hi = center + (float)K;

        u64 mlo = 0, mhi = 0;
        #pragma unroll
        for (int dy = 0; dy < K; dy++) {
            unsigned m = 0;
            #pragma unroll
            for (int dx = 0; dx < K; dx++) {
                float v = pl[dy * RW + dx];
                if (v >= lo && v <= hi) m |= (1u << dx);
            }
            int p = dy * STRIDE;
            if (p < 64) {
                mlo |= (u64)m << p;
                if (p + K > 64) mhi |= (u64)m >> (64 - p);
            } else {
                mhi |= (u64)m << (p - 64);
            }
        }

        const int ones = __popcll(mlo) + __popcll(mhi);
        int nc, best = KK - ones;

        if (!WIDE) {
            const u64 m = mlo;
            u64 neigh = (m << 1) | (m >> 1) | (m << 8) | (m >> 8);
            u64 iso = m & ~neigh;
            nc = __popcll(iso);
            u64 rem = m ^ iso;
            while (rem) {
                u64 cur = rem & (0ull - rem);
                while (true) {
                    u64 g1 = (cur | (cur << 1) | (cur >> 1) | (cur << 8) | (cur >> 8)) & rem;
                    u64 g2 = (g1 | (g1 << 1) | (g1 >> 1) | (g1 << 8) | (g1 >> 8)) & rem;
                    if (g2 == cur) break;
                    cur = g2;
                }
                int a = __popcll(cur);
                if (a > best) best = a;
                rem ^= cur;
                nc++;
            }
        } else {
            u64 nlo, nhi;
            expand128<K>(mlo, mhi, nlo, nhi);
            u64 isolo = mlo & ~nlo, isohi = mhi & ~nhi;
            nc = __popcll(isolo) + __popcll(isohi);
            u64 rlo = mlo ^ isolo, rhi = mhi ^ isohi;
            while (rlo | rhi) {
                u64 clo, chi;
                if (rlo) { clo = rlo & (0ull - rlo); chi = 0; }
                else     { clo = 0; chi = rhi & (0ull - rhi); }
                while (true) {
                    u64 elo, ehi, g1lo, g1hi, g2lo, g2hi;
                    expand128<K>(clo, chi, elo, ehi);
                    g1lo = (clo | elo) & rlo;
                    g1hi = (chi | ehi) & rhi;
                    expand128<K>(g1lo, g1hi, elo, ehi);
                    g2lo = (g1lo | elo) & rlo;
                    g2hi = (g1hi | ehi) & rhi;
                    if (g2lo == clo && g2hi == chi) break;
                    clo = g2lo; chi = g2hi;
                }
                int a = __popcll(clo) + __popcll(chi);
                if (a > best) best = a;
                rlo ^= clo; rhi ^= chi;
                nc++;
            }
        }

        // warp-aggregated per-channel histogram
        {
            int key = ch * 128 + ones;
            unsigned act   = __activemask();
            unsigned peers = __match_any_sync(act, key);
            if ((tid & 31) == (__ffs(peers) - 1))
                atomicAdd(&shh[key], __popc(peers));
        }
        tnc += nc;
        tpc += ((float)ones / (float)KK >= 0.59275f) ? 1 : 0;
        tma += best;
    }
    if (tnc | tpc | tma) {
        atomicAdd(&shs[cur_ch * 3 + 0], tnc);
        atomicAdd(&shs[cur_ch * 3 + 1], tpc);
        atomicAdd(&shs[cur_ch * 3 + 2], tma);
    }
    __syncthreads();

    // flush sparse partials to global accumulator
    for (int i = tid; i < 3 * 131; i += 512) {
        int ch = i / 131, q = i - ch * 131;
        int v = (q < 128) ? shh[ch * 128 + q] : shs[ch * 3 + (q - 128)];
        if (v) atomicAdd(&g_acc[(SEG * NPAIR + b * 3 + ch) * ACC_STRIDE + q], v);
    }
}

__global__ __launch_bounds__(512, 2) void patch_all_kernel(const float4* __restrict__ in4) {
    extern __shared__ float sm[];
    __shared__ int shh[3 * 128];
    __shared__ int shs[9];
    const int blk = blockIdx.x;   // heavy-first: k11,k9,k7,k5,k3
    if (blk < 1 * BPK)      patch_band<11, 3, 0>(in4, blk - 0 * BPK, sm, shh, shs);
    else if (blk < 2 * BPK) patch_band<9,  4, 1>(in4, blk - 1 * BPK, sm, shh, shs);
    else if (blk < 3 * BPK) patch_band<7,  5, 2>(in4, blk - 2 * BPK, sm, shh, shs);
    else if (blk < 4 * BPK) patch_band<5,  7, 3>(in4, blk - 3 * BPK, sm, shh, shs);
    else                    patch_band<3, 12, 4>(in4, blk - 4 * BPK, sm, shh, shs);
}

// ---------------------------------------------------------------------------
// Finalize: metrics -> g_feat, then self-zero g_acc for the next replay
// ---------------------------------------------------------------------------
__global__ void finalize_kernel() {
    int tid = blockIdx.x * blockDim.x + threadIdx.x;
    if (tid >= 5 * NPAIR) return;
    const int seg  = tid / NPAIR;
    const int pair = tid % NPAIR;
    const int b  = pair / 3;
    const int ch = pair % 3;

    const int K  = 11 - 2 * seg;     // seg order: 11,9,7,5,3
    const int KK = K * K;
    const int ROWS = (H + K - 1) / K;
    const int COLS = (W + K - 1) / K;
    const int P    = ROWS * COLS;

    int* acc = g_acc + (seg * NPAIR + pair) * ACC_STRIDE;
    const float fP = (float)P;
    float fd = 0.0f, m = 0.0f, m2 = 0.0f;
    for (int q = 0; q < KK; q++) {   // bin KK (fully on) dropped (tf bincount)
        float p = (float)acc[q] / fP;
        float n = (float)(q + 1);
        fd += p / n;
        m  += p * n;
        m2 += p * p * n;
    }
    float lac = (m2 - m * m) / (m * m);
    int acn  = acc[128] / P;
    int acp  = acc[129] / P;
    int acma = acc[130] / P;

    const int kidx = (K - 3) / 2;
    const int o = ((b * 5) * 5 + kidx) * 3 + ch;
    g_feat[o + 0 * 15] = (float)acn;
    g_feat[o + 1 * 15] = (float)acp;
    g_feat[o + 2 * 15] = (float)acma;
    g_feat[o + 3 * 15] = lac;
    g_feat[o + 4 * 15] = fd;

    for (int q = 0; q < 131; q++) acc[q] = 0;   // clean for next run
}

// ---------------------------------------------------------------------------
// Bilinear resize via smem pre-lerped rows, float4 LDS
// ---------------------------------------------------------------------------
#define RCHUNK 28
#define YBLKS (H / RCHUNK)   // 8
#define WC (W * 3)           // 672

__global__ __launch_bounds__(256) void resize_kernel(float* __restrict__ out) {
    __shared__ float feat[75];
    __shared__ __align__(16) float hrow[5 * WC];
    __shared__ float s_fy[RCHUNK];
    __shared__ int   s_y0[RCHUNK], s_y1[RCHUNK];

    const int b   = blockIdx.x / YBLKS;
    const int yc  = blockIdx.x % YBLKS;
    const int tid = threadIdx.x;

    if (tid < 75) feat[tid] = g_feat[b * 75 + tid];
    if (tid >= 96 && tid < 96 + RCHUNK) {
        int y = yc * RCHUNK + (tid - 96);
        float cy = ((float)y + 0.5f) * (5.0f / 224.0f) - 0.5f;
        float fl = floorf(cy);
        int y0 = (int)fl;
        float fy = cy - fl;
        int y0c = max(y0, 0), y1c = min(y0 + 1, 4);
        s_fy[tid - 96] = fy;
        s_y0[tid - 96] = y0c * WC;
        s_y1[tid - 96] = y1c * WC;
    }
    __syncthreads();

    for (int i = tid; i < 5 * WC; i += 256) {
        int r  = i / WC;
        int xc = i - r * WC;
        int x  = xc / 3;
        int ch = xc - x * 3;
        float cx = ((float)x + 0.5f) * (5.0f / 224.0f) - 0.5f;
        float fl = floorf(cx);
        int x0 = (int)fl;
        float fx = cx - fl;
        int x0c = max(x0, 0), x1c = min(x0 + 1, 4);
        float a  = feat[(r * 5 + x0c) * 3 + ch];
        float bb = feat[(r * 5 + x1c) * 3 + ch];
        hrow[i] = a + fx * (bb - a);
    }
    __syncthreads();

    float4* o4 = (float4*)(out + b * (H * WC) + yc * (RCHUNK * WC));
    const int N4 = RCHUNK * WC / 4;
    for (int i = tid; i < N4; i += 256) {
        int yl = i / (WC / 4);
        int x4 = i - yl * (WC / 4);
        const float4 a  = *(const float4*)&hrow[s_y0[yl] + 4 * x4];
        const float4 bb = *(const float4*)&hrow[s_y1[yl] + 4 * x4];
        const float fy = s_fy[yl];
        float4 v;
        v.x = a.x + fy * (bb.x - a.x);
        v.y = a.y + fy * (bb.y - a.y);
        v.z = a.z + fy * (bb.z - a.z);
        v.w = a.w + fy * (bb.w - a.w);
        o4[i] = v;
    }
}

// ---------------------------------------------------------------------------
extern "C" void kernel_launch(void* const* d_in, const int* in_sizes, int n_in,
                              void* d_out, int out_size) {
    const float4* in4 = (const float4*)d_in[0];
    float* out = (float*)d_out;

    cudaFuncSetAttribute(patch_all_kernel,
                         cudaFuncAttributeMaxDynamicSharedMemorySize, DYN_SMEM);
    patch_all_kernel<<<TOTAL_BLOCKS, 512, DYN_SMEM>>>(in4);
    finalize_kernel<<<(5 * NPAIR + 127) / 128, 128>>>();
    resize_kernel<<<BATCH * YBLKS, 256>>>(out);
}